// round 8
// baseline (speedup 1.0000x reference)
#include <cuda_runtime.h>
#include <cstdint>

#define B_    16
#define FIN_  16
#define FOUT_ 16
#define H_    384
#define W_    384
#define LAT_  512
#define NMIX_ 8
#define HW_   (H_ * W_)        // 147456
#define PLANE4_ (HW_ / 4)      // 36864 float4 groups per channel plane

__device__ __forceinline__ unsigned long long pack2(float v) {
    unsigned int u = __float_as_uint(v);
    return ((unsigned long long)u << 32) | (unsigned long long)u;
}

__device__ __forceinline__ unsigned long long ffma2(unsigned long long a,
                                                    unsigned long long b,
                                                    unsigned long long c) {
    unsigned long long d;
    asm("fma.rn.f32x2 %0, %1, %2, %3;" : "=l"(d) : "l"(a), "l"(b), "l"(c));
    return d;
}

// ---------------------------------------------------------------------------
// Fused kernel, float4 body, occupancy 3 (85-reg cap), LDS.128 k-loads.
//   Phase 1 (per block): warp m computes mix[b][m]; 256 threads build the
//   16x16 per-sample kernel + bias in smem, packed {k,k}. Registers die
//   before phase 2.
//   Phase 2: one float4 pixel group per thread: 16 LDG.128 in,
//   128 LDS.128 k-pair loads, 512 ffma2, 16 STG.128 out.
// ---------------------------------------------------------------------------
__global__ void __launch_bounds__(256, 3)
mixconv_fused(const float* __restrict__ x,
              const float* __restrict__ lat,
              const float* __restrict__ kernel_mix,
              const float* __restrict__ bias_mix,
              const float* __restrict__ w_dyn,
              const float* __restrict__ b_dyn,
              float* __restrict__ out) {
    __shared__ float s_mix[NMIX_];
    __shared__ __align__(16) unsigned long long sk[FOUT_ * FIN_]; // packed {k,k}
    __shared__ unsigned long long sb[FOUT_];

    const int b    = blockIdx.y;
    const int t    = threadIdx.x;
    const int w    = t >> 5;      // warp id 0..7 == mixture index
    const int lane = t & 31;

    // ---- Phase 1a: mix[b][w] via warp-parallel dot product -------------
    {
        const float* __restrict__ lp = lat + b * LAT_;
        const float* __restrict__ wp = w_dyn + w * LAT_;
        float s = 0.f;
        #pragma unroll
        for (int j = 0; j < LAT_ / 32; ++j)
            s = fmaf(__ldg(lp + lane + 32 * j), __ldg(wp + lane + 32 * j), s);
        #pragma unroll
        for (int off = 16; off > 0; off >>= 1)
            s += __shfl_xor_sync(0xffffffffu, s, off);
        if (lane == 0) s_mix[w] = s + __ldg(b_dyn + w);
    }
    __syncthreads();

    // ---- Phase 1b: per-sample kernel + bias into smem ------------------
    {
        float s = 0.f;
        #pragma unroll
        for (int m = 0; m < NMIX_; ++m)
            s = fmaf(s_mix[m], __ldg(kernel_mix + m * (FOUT_ * FIN_) + t), s);
        sk[t] = pack2(s);
        if (t < FOUT_) {
            float sv = 0.f;
            #pragma unroll
            for (int m = 0; m < NMIX_; ++m)
                sv = fmaf(s_mix[m], __ldg(bias_mix + m * FOUT_ + t), sv);
            sb[t] = pack2(sv);
        }
    }
    __syncthreads();

    // ---- Phase 2: one float4 streaming tile ----------------------------
    const int p = blockIdx.x * 256 + t;             // float4 group in plane

    const ulonglong2* __restrict__ xp =
        (const ulonglong2*)(x + (size_t)b * FIN_ * HW_);
    ulonglong2* __restrict__ op =
        (ulonglong2*)(out + (size_t)b * FOUT_ * HW_);
    const ulonglong2* __restrict__ sk2 = (const ulonglong2*)sk;

    unsigned long long in_lo[FIN_], in_hi[FIN_];
    #pragma unroll
    for (int i = 0; i < FIN_; ++i) {
        ulonglong2 v = xp[(size_t)i * PLANE4_ + p];
        in_lo[i] = v.x;
        in_hi[i] = v.y;
    }

    #pragma unroll
    for (int o = 0; o < FOUT_; ++o) {
        unsigned long long alo = sb[o];
        unsigned long long ahi = alo;
        #pragma unroll
        for (int j = 0; j < FIN_ / 2; ++j) {
            ulonglong2 kk = sk2[o * (FIN_ / 2) + j];   // LDS.128: two {k,k}
            alo = ffma2(kk.x, in_lo[2 * j],     alo);
            ahi = ffma2(kk.x, in_hi[2 * j],     ahi);
            alo = ffma2(kk.y, in_lo[2 * j + 1], alo);
            ahi = ffma2(kk.y, in_hi[2 * j + 1], ahi);
        }
        ulonglong2 r;
        r.x = alo;
        r.y = ahi;
        op[(size_t)o * PLANE4_ + p] = r;
    }
}

// ---------------------------------------------------------------------------
extern "C" void kernel_launch(void* const* d_in, const int* in_sizes, int n_in,
                              void* d_out, int out_size) {
    const float* x          = (const float*)d_in[0];  // [16,16,384,384]
    const float* lat        = (const float*)d_in[1];  // [16,512]
    const float* kernel_mix = (const float*)d_in[2];  // [8,16,16]
    const float* bias_mix   = (const float*)d_in[3];  // [8,16]
    const float* w_dyn      = (const float*)d_in[4];  // [8,512]
    const float* b_dyn      = (const float*)d_in[5];  // [8]
    float* out = (float*)d_out;

    dim3 grid(PLANE4_ / 256, B_);   // (144, 16) = 2304 blocks, one tile each
    mixconv_fused<<<grid, 256>>>(x, lat, kernel_mix, bias_mix, w_dyn, b_dyn, out);
}

// round 12
// speedup vs baseline: 1.0209x; 1.0209x over previous
#include <cuda_runtime.h>
#include <cstdint>

#define B_    16
#define FIN_  16
#define FOUT_ 16
#define H_    384
#define W_    384
#define LAT_  512
#define NMIX_ 8
#define HW_   (H_ * W_)        // 147456
#define PLANE4_ (HW_ / 4)      // 36864 float4 groups per channel plane
#define GX_    9               // x-blocks
#define TILES_ 16              // tiles per CTA: 9*16 = 144 tile positions/plane

__device__ __forceinline__ unsigned long long pack2(float v) {
    unsigned int u = __float_as_uint(v);
    return ((unsigned long long)u << 32) | (unsigned long long)u;
}

__device__ __forceinline__ unsigned long long ffma2(unsigned long long a,
                                                    unsigned long long b,
                                                    unsigned long long c) {
    unsigned long long d;
    asm("fma.rn.f32x2 %0, %1, %2, %3;" : "=l"(d) : "l"(a), "l"(b), "l"(c));
    return d;
}

__device__ __forceinline__ void prefetch_l2(const void* p) {
    asm volatile("prefetch.global.L2 [%0];" :: "l"(p));
}

// ---------------------------------------------------------------------------
// Fused persistent kernel: 144 CTAs (1/SM), 256 threads, 16 tiles each.
//   Phase 1 (once per CTA): warp-parallel mix -> per-sample K + bias in smem.
//   Phase 2 loop: prefetch.global.L2 for tile t+1 (no reg dest, keeps DRAM
//   busy through the compute tail), then the proven float4 body on tile t
//   whose LDGs now hit L2. occ=1 CTA -> 255-reg budget -> no spill with loop.
// ---------------------------------------------------------------------------
__global__ void __launch_bounds__(256, 1)
mixconv_fused(const float* __restrict__ x,
              const float* __restrict__ lat,
              const float* __restrict__ kernel_mix,
              const float* __restrict__ bias_mix,
              const float* __restrict__ w_dyn,
              const float* __restrict__ b_dyn,
              float* __restrict__ out) {
    __shared__ float s_mix[NMIX_];
    __shared__ __align__(16) unsigned long long sk[FOUT_ * FIN_]; // packed {k,k}
    __shared__ unsigned long long sb[FOUT_];

    const int b    = blockIdx.y;
    const int t    = threadIdx.x;
    const int w    = t >> 5;
    const int lane = t & 31;

    // ---- Phase 1a: mix[b][w] via warp-parallel dot product -------------
    {
        const float* __restrict__ lp = lat + b * LAT_;
        const float* __restrict__ wp = w_dyn + w * LAT_;
        float s = 0.f;
        #pragma unroll
        for (int j = 0; j < LAT_ / 32; ++j)
            s = fmaf(__ldg(lp + lane + 32 * j), __ldg(wp + lane + 32 * j), s);
        #pragma unroll
        for (int off = 16; off > 0; off >>= 1)
            s += __shfl_xor_sync(0xffffffffu, s, off);
        if (lane == 0) s_mix[w] = s + __ldg(b_dyn + w);
    }
    __syncthreads();

    // ---- Phase 1b: per-sample kernel + bias into smem ------------------
    {
        float s = 0.f;
        #pragma unroll
        for (int m = 0; m < NMIX_; ++m)
            s = fmaf(s_mix[m], __ldg(kernel_mix + m * (FOUT_ * FIN_) + t), s);
        sk[t] = pack2(s);
        if (t < FOUT_) {
            float sv = 0.f;
            #pragma unroll
            for (int m = 0; m < NMIX_; ++m)
                sv = fmaf(s_mix[m], __ldg(bias_mix + m * FOUT_ + t), sv);
            sb[t] = pack2(sv);
        }
    }
    __syncthreads();

    // ---- Phase 2: 16 tiles with one-tile-ahead L2 prefetch -------------
    const ulonglong2* __restrict__ xp =
        (const ulonglong2*)(x + (size_t)b * FIN_ * HW_);
    ulonglong2* __restrict__ op =
        (ulonglong2*)(out + (size_t)b * FOUT_ * HW_);
    const ulonglong2* __restrict__ sk2 = (const ulonglong2*)sk;

    #pragma unroll 1
    for (int it = 0; it < TILES_; ++it) {
        const int p = (blockIdx.x * TILES_ + it) * 256 + t;

        // Prefetch next tile's 16 channel lines into L2 (overlaps this
        // tile's compute; no register/scoreboard cost).
        if (it + 1 < TILES_) {
            const int pn = p + 256;
            #pragma unroll
            for (int i = 0; i < FIN_; ++i)
                prefetch_l2(xp + (size_t)i * PLANE4_ + pn);
        }

        // Load current tile (L2 hits for it>0).
        unsigned long long in_lo[FIN_], in_hi[FIN_];
        #pragma unroll
        for (int i = 0; i < FIN_; ++i) {
            ulonglong2 v = xp[(size_t)i * PLANE4_ + p];
            in_lo[i] = v.x;
            in_hi[i] = v.y;
        }

        #pragma unroll
        for (int o = 0; o < FOUT_; ++o) {
            unsigned long long alo = sb[o];
            unsigned long long ahi = alo;
            #pragma unroll
            for (int j = 0; j < FIN_ / 2; ++j) {
                ulonglong2 kk = sk2[o * (FIN_ / 2) + j];   // LDS.128 broadcast
                alo = ffma2(kk.x, in_lo[2 * j],     alo);
                ahi = ffma2(kk.x, in_hi[2 * j],     ahi);
                alo = ffma2(kk.y, in_lo[2 * j + 1], alo);
                ahi = ffma2(kk.y, in_hi[2 * j + 1], ahi);
            }
            ulonglong2 r;
            r.x = alo;
            r.y = ahi;
            op[(size_t)o * PLANE4_ + p] = r;
        }
    }
}

// ---------------------------------------------------------------------------
extern "C" void kernel_launch(void* const* d_in, const int* in_sizes, int n_in,
                              void* d_out, int out_size) {
    const float* x          = (const float*)d_in[0];  // [16,16,384,384]
    const float* lat        = (const float*)d_in[1];  // [16,512]
    const float* kernel_mix = (const float*)d_in[2];  // [8,16,16]
    const float* bias_mix   = (const float*)d_in[3];  // [8,16]
    const float* w_dyn      = (const float*)d_in[4];  // [8,512]
    const float* b_dyn      = (const float*)d_in[5];  // [8]
    float* out = (float*)d_out;

    dim3 grid(GX_, B_);   // (9, 16) = 144 CTAs, one per SM, 16 tiles each
    mixconv_fused<<<grid, 256>>>(x, lat, kernel_mix, bias_mix, w_dyn, b_dyn, out);
}

// round 13
// speedup vs baseline: 1.1427x; 1.1193x over previous
#include <cuda_runtime.h>
#include <cstdint>

#define B_    16
#define FIN_  16
#define FOUT_ 16
#define H_    384
#define W_    384
#define LAT_  512
#define NMIX_ 8
#define HW_   (H_ * W_)        // 147456
#define PLANE4_ (HW_ / 4)      // 36864 float4 groups per channel plane

__device__ __forceinline__ unsigned long long pack2(float v) {
    unsigned int u = __float_as_uint(v);
    return ((unsigned long long)u << 32) | (unsigned long long)u;
}

__device__ __forceinline__ unsigned long long ffma2(unsigned long long a,
                                                    unsigned long long b,
                                                    unsigned long long c) {
    unsigned long long d;
    asm("fma.rn.f32x2 %0, %1, %2, %3;" : "=l"(d) : "l"(a), "l"(b), "l"(c));
    return d;
}

// ---------------------------------------------------------------------------
// Fused kernel, software-pipelined start:
//   (0) issue the 16 x-tile LDG.128 FIRST (depend only on b,p);
//   (1) while those DRAM loads are in flight, run phase-1: warp-parallel
//       mix dot products + per-sample K/bias build into smem (barriers drain
//       STS, not LDG — the scoreboard wait lands at first consumption);
//   (2) ffma2 streaming body consumes the loads, which have arrived by then.
//   Phase-1 cost (~900 cyc) is hidden behind the ~600+ cyc x-load latency.
//   occ 2 (128-reg budget): 64 in-flight load regs + phase-1 live fits.
// ---------------------------------------------------------------------------
__global__ void __launch_bounds__(256, 2)
mixconv_fused(const float* __restrict__ x,
              const float* __restrict__ lat,
              const float* __restrict__ kernel_mix,
              const float* __restrict__ bias_mix,
              const float* __restrict__ w_dyn,
              const float* __restrict__ b_dyn,
              float* __restrict__ out) {
    __shared__ float s_mix[NMIX_];
    __shared__ __align__(16) unsigned long long sk[FOUT_ * FIN_]; // packed {k,k}
    __shared__ unsigned long long sb[FOUT_];

    const int b    = blockIdx.y;
    const int t    = threadIdx.x;
    const int w    = t >> 5;      // warp id 0..7 == mixture index
    const int lane = t & 31;

    // ---- (0) Issue x-tile loads first: independent of phase-1 ----------
    const int p = blockIdx.x * 256 + t;             // float4 group in plane

    const ulonglong2* __restrict__ xp =
        (const ulonglong2*)(x + (size_t)b * FIN_ * HW_);
    ulonglong2* __restrict__ op =
        (ulonglong2*)(out + (size_t)b * FOUT_ * HW_);
    const ulonglong2* __restrict__ sk2 = (const ulonglong2*)sk;

    unsigned long long in_lo[FIN_], in_hi[FIN_];
    #pragma unroll
    for (int i = 0; i < FIN_; ++i) {
        ulonglong2 v = xp[(size_t)i * PLANE4_ + p];
        in_lo[i] = v.x;
        in_hi[i] = v.y;
    }

    // ---- (1a) mix[b][w] via warp-parallel dot product (overlaps loads) --
    {
        const float* __restrict__ lp = lat + b * LAT_;
        const float* __restrict__ wp = w_dyn + w * LAT_;
        float s = 0.f;
        #pragma unroll
        for (int j = 0; j < LAT_ / 32; ++j)
            s = fmaf(__ldg(lp + lane + 32 * j), __ldg(wp + lane + 32 * j), s);
        #pragma unroll
        for (int off = 16; off > 0; off >>= 1)
            s += __shfl_xor_sync(0xffffffffu, s, off);
        if (lane == 0) s_mix[w] = s + __ldg(b_dyn + w);
    }
    __syncthreads();

    // ---- (1b) per-sample kernel + bias into smem ------------------------
    {
        float s = 0.f;
        #pragma unroll
        for (int m = 0; m < NMIX_; ++m)
            s = fmaf(s_mix[m], __ldg(kernel_mix + m * (FOUT_ * FIN_) + t), s);
        sk[t] = pack2(s);
        if (t < FOUT_) {
            float sv = 0.f;
            #pragma unroll
            for (int m = 0; m < NMIX_; ++m)
                sv = fmaf(s_mix[m], __ldg(bias_mix + m * FOUT_ + t), sv);
            sb[t] = pack2(sv);
        }
    }
    __syncthreads();

    // ---- (2) streaming body: consume loads (arrived during phase-1) -----
    #pragma unroll
    for (int o = 0; o < FOUT_; ++o) {
        unsigned long long alo = sb[o];
        unsigned long long ahi = alo;
        #pragma unroll
        for (int j = 0; j < FIN_ / 2; ++j) {
            ulonglong2 kk = sk2[o * (FIN_ / 2) + j];   // LDS.128: two {k,k}
            alo = ffma2(kk.x, in_lo[2 * j],     alo);
            ahi = ffma2(kk.x, in_hi[2 * j],     ahi);
            alo = ffma2(kk.y, in_lo[2 * j + 1], alo);
            ahi = ffma2(kk.y, in_hi[2 * j + 1], ahi);
        }
        ulonglong2 r;
        r.x = alo;
        r.y = ahi;
        op[(size_t)o * PLANE4_ + p] = r;
    }
}

// ---------------------------------------------------------------------------
extern "C" void kernel_launch(void* const* d_in, const int* in_sizes, int n_in,
                              void* d_out, int out_size) {
    const float* x          = (const float*)d_in[0];  // [16,16,384,384]
    const float* lat        = (const float*)d_in[1];  // [16,512]
    const float* kernel_mix = (const float*)d_in[2];  // [8,16,16]
    const float* bias_mix   = (const float*)d_in[3];  // [8,16]
    const float* w_dyn      = (const float*)d_in[4];  // [8,512]
    const float* b_dyn      = (const float*)d_in[5];  // [8]
    float* out = (float*)d_out;

    dim3 grid(PLANE4_ / 256, B_);   // (144, 16) = 2304 blocks, one tile each
    mixconv_fused<<<grid, 256>>>(x, lat, kernel_mix, bias_mix, w_dyn, b_dyn, out);
}